// round 1
// baseline (speedup 1.0000x reference)
#include <cuda_runtime.h>
#include <math.h>

#define M 5
#define EPS_F 1e-5f
#define NACC 20              // cond_g[5] + upper-triangle G[15]
#define NBLOCKS 1184         // 148 SMs * 8
#define NTHREADS 256

__device__ float  g_W[M * M];        // whitening matrix rows
__device__ float  g_mask[M];         // kept singular directions
__device__ double g_partials[NBLOCKS * NACC];
__device__ double g_acc[NACC];
__device__ float  g_x[M];            // solve result

// ---------------------------------------------------------------------------
// Kernel 1: 5x5 symmetric Jacobi eigendecomposition of K -> W = diag(s^-1/2) V^T
// ---------------------------------------------------------------------------
__global__ void kwng_setup(const float* __restrict__ K) {
    double a[M][M], v[M][M];
    for (int i = 0; i < M; i++)
        for (int j = 0; j < M; j++) {
            a[i][j] = (double)K[i * M + j];
            v[i][j] = (i == j) ? 1.0 : 0.0;
        }
    for (int sweep = 0; sweep < 60; sweep++) {
        double off = 0.0;
        for (int p = 0; p < M; p++)
            for (int q = p + 1; q < M; q++) off += a[p][q] * a[p][q];
        if (off < 1e-28) break;
        for (int p = 0; p < M; p++) {
            for (int q = p + 1; q < M; q++) {
                double apq = a[p][q];
                if (fabs(apq) < 1e-300) continue;
                double theta = (a[q][q] - a[p][p]) / (2.0 * apq);
                double t = ((theta >= 0.0) ? 1.0 : -1.0) /
                           (fabs(theta) + sqrt(theta * theta + 1.0));
                double c = 1.0 / sqrt(t * t + 1.0);
                double s = t * c;
                for (int k = 0; k < M; k++) {   // right-rotate columns
                    double akp = a[k][p], akq = a[k][q];
                    a[k][p] = c * akp - s * akq;
                    a[k][q] = s * akp + c * akq;
                }
                for (int k = 0; k < M; k++) {   // left-rotate rows
                    double apk = a[p][k], aqk = a[q][k];
                    a[p][k] = c * apk - s * aqk;
                    a[q][k] = s * apk + c * aqk;
                }
                for (int k = 0; k < M; k++) {   // accumulate eigenvectors
                    double vkp = v[k][p], vkq = v[k][q];
                    v[k][p] = c * vkp - s * vkq;
                    v[k][q] = s * vkp + c * vkq;
                }
            }
        }
    }
    // eigenvalues on diag(a); eigenvector i = column i of v
    for (int i = 0; i < M; i++) {
        double si = a[i][i];
        bool keep = si > 0.0;                   // THRESH = 0
        g_mask[i] = keep ? 1.0f : 0.0f;
        double w = keep ? 1.0 / sqrt(si) : 0.0; // sqrt(1/s)
        for (int j = 0; j < M; j++)
            g_W[i * M + j] = (float)(w * v[j][i]);
    }
}

// ---------------------------------------------------------------------------
// Kernel 2: streaming reduction pass over D
//   Tt_i = sum_j W_ij T_jd ;  Dv = 1/(||Tt_col|| + 1e-8)
//   cond_g_i += Tt_i * Dv * g_d ;  G_ij += Tt_i * Dv * Tt_j
// ---------------------------------------------------------------------------
__global__ void __launch_bounds__(NTHREADS)
kwng_pass1(const float* __restrict__ T, const float* __restrict__ g, int D) {
    float W[M * M];
#pragma unroll
    for (int i = 0; i < M * M; i++) W[i] = g_W[i];

    float acc[NACC];
#pragma unroll
    for (int a = 0; a < NACC; a++) acc[a] = 0.0f;

    const float4* __restrict__ T4 = (const float4*)T;
    const float4* __restrict__ g4 = (const float4*)g;
    const int n4 = D >> 2;
    const int row4 = D >> 2;

    for (int idx = blockIdx.x * blockDim.x + threadIdx.x; idx < n4;
         idx += gridDim.x * blockDim.x) {
        float4 t[M];
#pragma unroll
        for (int j = 0; j < M; j++) t[j] = T4[(size_t)j * row4 + idx];
        float4 gv = g4[idx];
        const float* tp = reinterpret_cast<const float*>(t);
        const float* gp = reinterpret_cast<const float*>(&gv);
#pragma unroll
        for (int lane = 0; lane < 4; lane++) {
            float tj[M], tt[M];
#pragma unroll
            for (int j = 0; j < M; j++) tj[j] = tp[j * 4 + lane];
#pragma unroll
            for (int i = 0; i < M; i++) {
                float s = W[i * M + 0] * tj[0];
#pragma unroll
                for (int j = 1; j < M; j++) s = fmaf(W[i * M + j], tj[j], s);
                tt[i] = s;
            }
            float ss = tt[0] * tt[0];
#pragma unroll
            for (int i = 1; i < M; i++) ss = fmaf(tt[i], tt[i], ss);
            float dv = 1.0f / (sqrtf(ss) + 1e-8f);
            float dvg = dv * gp[lane];
#pragma unroll
            for (int i = 0; i < M; i++) acc[i] = fmaf(tt[i], dvg, acc[i]);
            int k = M;
#pragma unroll
            for (int i = 0; i < M; i++) {
                float ti_dv = tt[i] * dv;
#pragma unroll
                for (int j = 0; j < M; j++) {
                    if (j >= i) { acc[k] = fmaf(ti_dv, tt[j], acc[k]); k++; }
                }
            }
        }
    }

    // warp tree-reduce, then fixed-order block sum -> per-block partial (deterministic)
    __shared__ float sred[NTHREADS / 32][NACC];
    int lane = threadIdx.x & 31;
    int warp = threadIdx.x >> 5;
#pragma unroll
    for (int a = 0; a < NACC; a++) {
        float v = acc[a];
#pragma unroll
        for (int off = 16; off > 0; off >>= 1)
            v += __shfl_down_sync(0xffffffffu, v, off);
        if (lane == 0) sred[warp][a] = v;
    }
    __syncthreads();
    if (threadIdx.x < NACC) {
        double s = 0.0;
#pragma unroll
        for (int w = 0; w < NTHREADS / 32; w++) s += (double)sred[w][threadIdx.x];
        g_partials[(size_t)blockIdx.x * NACC + threadIdx.x] = s;
    }
}

// ---------------------------------------------------------------------------
// Kernel 3: fixed-order reduction of per-block partials (20 warps, 1 block)
// ---------------------------------------------------------------------------
__global__ void kwng_reduce() {
    int a = threadIdx.x >> 5;    // accumulator index 0..19
    int lane = threadIdx.x & 31;
    double s = 0.0;
    for (int b = lane; b < NBLOCKS; b += 32)
        s += g_partials[(size_t)b * NACC + a];
#pragma unroll
    for (int off = 16; off > 0; off >>= 1)
        s += __shfl_down_sync(0xffffffffu, s, off);
    if (lane == 0) g_acc[a] = s;
}

// ---------------------------------------------------------------------------
// Kernel 4: form G (+ eps*diag(mask)), solve 5x5 in double, store x
// ---------------------------------------------------------------------------
__global__ void kwng_solve() {
    double G[M][M], b[M];
    for (int i = 0; i < M; i++) b[i] = g_acc[i];
    int k = M;
    for (int i = 0; i < M; i++)
        for (int j = i; j < M; j++) {
            G[i][j] = g_acc[k];
            G[j][i] = g_acc[k];
            k++;
        }
    for (int i = 0; i < M; i++) G[i][i] += 1e-5 * (double)g_mask[i];

    // Gaussian elimination with partial pivoting
    for (int col = 0; col < M; col++) {
        int piv = col;
        for (int r = col + 1; r < M; r++)
            if (fabs(G[r][col]) > fabs(G[piv][col])) piv = r;
        if (piv != col) {
            for (int c = 0; c < M; c++) {
                double tmp = G[col][c]; G[col][c] = G[piv][c]; G[piv][c] = tmp;
            }
            double tb = b[col]; b[col] = b[piv]; b[piv] = tb;
        }
        double inv = 1.0 / G[col][col];
        for (int r = col + 1; r < M; r++) {
            double f = G[r][col] * inv;
            for (int c = col; c < M; c++) G[r][c] -= f * G[col][c];
            b[r] -= f * b[col];
        }
    }
    double x[M];
    for (int r = M - 1; r >= 0; r--) {
        double s = b[r];
        for (int c = r + 1; c < M; c++) s -= G[r][c] * x[c];
        x[r] = s / G[r][r];
    }
    for (int i = 0; i < M; i++) g_x[i] = (float)x[i];
}

// ---------------------------------------------------------------------------
// Kernel 5: map pass: out = Dv * (g + Tt . x) / eps     (beta = -1)
// ---------------------------------------------------------------------------
__global__ void __launch_bounds__(NTHREADS)
kwng_pass2(const float* __restrict__ T, const float* __restrict__ g,
           float* __restrict__ out, int D) {
    float W[M * M], x[M];
#pragma unroll
    for (int i = 0; i < M * M; i++) W[i] = g_W[i];
#pragma unroll
    for (int i = 0; i < M; i++) x[i] = g_x[i];

    const float4* __restrict__ T4 = (const float4*)T;
    const float4* __restrict__ g4 = (const float4*)g;
    float4* __restrict__ o4 = (float4*)out;
    const int n4 = D >> 2;
    const int row4 = D >> 2;

    for (int idx = blockIdx.x * blockDim.x + threadIdx.x; idx < n4;
         idx += gridDim.x * blockDim.x) {
        float4 t[M];
#pragma unroll
        for (int j = 0; j < M; j++) t[j] = T4[(size_t)j * row4 + idx];
        float4 gv = g4[idx];
        const float* tp = reinterpret_cast<const float*>(t);
        const float* gp = reinterpret_cast<const float*>(&gv);
        float4 ov;
        float* op = reinterpret_cast<float*>(&ov);
#pragma unroll
        for (int lane = 0; lane < 4; lane++) {
            float tj[M], tt[M];
#pragma unroll
            for (int j = 0; j < M; j++) tj[j] = tp[j * 4 + lane];
#pragma unroll
            for (int i = 0; i < M; i++) {
                float s = W[i * M + 0] * tj[0];
#pragma unroll
                for (int j = 1; j < M; j++) s = fmaf(W[i * M + j], tj[j], s);
                tt[i] = s;
            }
            float ss = tt[0] * tt[0];
#pragma unroll
            for (int i = 1; i < M; i++) ss = fmaf(tt[i], tt[i], ss);
            float dv = 1.0f / (sqrtf(ss) + 1e-8f);
            float cond = tt[0] * x[0];
#pragma unroll
            for (int i = 1; i < M; i++) cond = fmaf(tt[i], x[i], cond);
            op[lane] = dv * ((gp[lane] + cond) / EPS_F);
        }
        o4[idx] = ov;
    }
}

// ---------------------------------------------------------------------------
extern "C" void kernel_launch(void* const* d_in, const int* in_sizes, int n_in,
                              void* d_out, int out_size) {
    const float* K = (const float*)d_in[0];   // [5,5]
    const float* T = (const float*)d_in[1];   // [5, D]
    const float* g = (const float*)d_in[2];   // [D]
    float* out = (float*)d_out;               // [D]
    int D = in_sizes[2];

    kwng_setup<<<1, 1>>>(K);
    kwng_pass1<<<NBLOCKS, NTHREADS>>>(T, g, D);
    kwng_reduce<<<1, NACC * 32>>>();
    kwng_solve<<<1, 1>>>();
    kwng_pass2<<<NBLOCKS, NTHREADS>>>(T, g, out, D);
}

// round 2
// speedup vs baseline: 2.1303x; 2.1303x over previous
#include <cuda_runtime.h>
#include <math.h>

#define M 5
#define NACC 20              // c[5] + packed upper Gram S[15]
#define NBLOCKS 1332         // 148 SMs * 3 blocks * 3 waves
#define NTHREADS 256

__device__ float  g_W[M * M];        // whitening matrix rows: W = diag(s^-1/2) V^T
__device__ float  g_qpk[15];         // Q = W^T W packed upper, off-diag pre-doubled
__device__ float  g_mask[M];
__device__ float  g_y[M];            // y = W^T z (pass2 contraction vector)
__device__ double g_partials[NBLOCKS * NACC];

// ---------------------------------------------------------------------------
// Kernel 1: fp32 5x5 Jacobi eigendecomposition -> W, mask, Q packed
// ---------------------------------------------------------------------------
__global__ void kwng_setup(const float* __restrict__ K) {
    float a[M][M], v[M][M];
    for (int i = 0; i < M; i++)
        for (int j = 0; j < M; j++) {
            a[i][j] = K[i * M + j];
            v[i][j] = (i == j) ? 1.0f : 0.0f;
        }
    for (int sweep = 0; sweep < 15; sweep++) {
        float off = 0.0f;
        for (int p = 0; p < M; p++)
            for (int q = p + 1; q < M; q++) off += a[p][q] * a[p][q];
        if (off < 1e-18f) break;
        for (int p = 0; p < M; p++) {
            for (int q = p + 1; q < M; q++) {
                float apq = a[p][q];
                if (fabsf(apq) < 1e-30f) continue;
                float theta = (a[q][q] - a[p][p]) / (2.0f * apq);
                float t = ((theta >= 0.0f) ? 1.0f : -1.0f) /
                          (fabsf(theta) + sqrtf(theta * theta + 1.0f));
                float c = 1.0f / sqrtf(t * t + 1.0f);
                float s = t * c;
                for (int k = 0; k < M; k++) {
                    float akp = a[k][p], akq = a[k][q];
                    a[k][p] = c * akp - s * akq;
                    a[k][q] = s * akp + c * akq;
                }
                for (int k = 0; k < M; k++) {
                    float apk = a[p][k], aqk = a[q][k];
                    a[p][k] = c * apk - s * aqk;
                    a[q][k] = s * apk + c * aqk;
                }
                for (int k = 0; k < M; k++) {
                    float vkp = v[k][p], vkq = v[k][q];
                    v[k][p] = c * vkp - s * vkq;
                    v[k][q] = s * vkp + c * vkq;
                }
            }
        }
    }
    float W[M][M];
    for (int i = 0; i < M; i++) {
        float si = a[i][i];
        bool keep = si > 0.0f;                    // THRESH = 0
        g_mask[i] = keep ? 1.0f : 0.0f;
        float w = keep ? (1.0f / sqrtf(si)) : 0.0f;
        for (int j = 0; j < M; j++) {
            W[i][j] = w * v[j][i];
            g_W[i * M + j] = W[i][j];
        }
    }
    // Q = W^T W (symmetric). Pack upper triangle row-major; off-diag doubled.
    int qi = 0;
    for (int j = 0; j < M; j++)
        for (int k = j; k < M; k++) {
            float q = 0.0f;
            for (int i = 0; i < M; i++) q += W[i][j] * W[i][k];
            g_qpk[qi++] = (k == j) ? q : 2.0f * q;
        }
}

// ---------------------------------------------------------------------------
// Kernel 2: streaming reduction in raw T basis
//   ss = t^T Q t ; dv = 1/(sqrt(ss)+1e-8)
//   c_j += dv*g*t_j ; S_jk += dv*t_j*t_k  (packed upper)
// ---------------------------------------------------------------------------
__global__ void __launch_bounds__(NTHREADS, 3)
kwng_pass1(const float* __restrict__ T, const float* __restrict__ g, int D) {
    float qpk[15];
#pragma unroll
    for (int i = 0; i < 15; i++) qpk[i] = g_qpk[i];

    float acc[NACC];
#pragma unroll
    for (int a = 0; a < NACC; a++) acc[a] = 0.0f;

    const float4* __restrict__ T4 = (const float4*)T;
    const float4* __restrict__ g4 = (const float4*)g;
    const int n4 = D >> 2;

    for (int idx = blockIdx.x * blockDim.x + threadIdx.x; idx < n4;
         idx += gridDim.x * blockDim.x) {
        float4 tv[M];
#pragma unroll
        for (int j = 0; j < M; j++) tv[j] = T4[(size_t)j * n4 + idx];
        float4 gv = g4[idx];
        const float* tp = reinterpret_cast<const float*>(tv);
        const float* gp = reinterpret_cast<const float*>(&gv);
#pragma unroll
        for (int lane = 0; lane < 4; lane++) {
            float t[M];
#pragma unroll
            for (int j = 0; j < M; j++) t[j] = tp[j * 4 + lane];
            // ss = t^T Q t via packed upper (off-diag doubled)
            float ss = 0.0f;
            int qi = 0;
#pragma unroll
            for (int j = 0; j < M; j++) {
                float inner = qpk[qi++] * t[j];
#pragma unroll
                for (int k = j + 1; k < M; k++)
                    inner = fmaf(qpk[qi++], t[k], inner);
                ss = fmaf(inner, t[j], ss);
            }
            float r  = rsqrtf(fmaxf(ss, 1e-37f));
            float dv = __fdividef(1.0f, fmaf(ss, r, 1e-8f));
            float dvg = dv * gp[lane];
#pragma unroll
            for (int j = 0; j < M; j++) acc[j] = fmaf(t[j], dvg, acc[j]);
            int ai = M;
#pragma unroll
            for (int j = 0; j < M; j++) {
                float u = dv * t[j];
#pragma unroll
                for (int k = j; k < M; k++) {
                    acc[ai] = fmaf(u, t[k], acc[ai]);
                    ai++;
                }
            }
        }
    }

    // deterministic block reduction
    __shared__ float sred[NTHREADS / 32][NACC];
    int lane = threadIdx.x & 31;
    int warp = threadIdx.x >> 5;
#pragma unroll
    for (int a = 0; a < NACC; a++) {
        float v = acc[a];
#pragma unroll
        for (int off = 16; off > 0; off >>= 1)
            v += __shfl_down_sync(0xffffffffu, v, off);
        if (lane == 0) sred[warp][a] = v;
    }
    __syncthreads();
    if (threadIdx.x < NACC) {
        double s = 0.0;
#pragma unroll
        for (int w = 0; w < NTHREADS / 32; w++) s += (double)sred[w][threadIdx.x];
        g_partials[(size_t)blockIdx.x * NACC + threadIdx.x] = s;
    }
}

// ---------------------------------------------------------------------------
// Kernel 3: reduce partials + tiny solve (640 threads, 1 block)
//   G = W S W^T + eps*diag(mask);  z = G^{-1} (W c);  y = W^T z
// ---------------------------------------------------------------------------
__global__ void kwng_reduce_solve() {
    __shared__ double sacc[NACC];
    int a = threadIdx.x >> 5;
    int lane = threadIdx.x & 31;
    if (a < NACC) {
        double s = 0.0;
        for (int b = lane; b < NBLOCKS; b += 32)
            s += g_partials[(size_t)b * NACC + a];
#pragma unroll
        for (int off = 16; off > 0; off >>= 1)
            s += __shfl_down_sync(0xffffffffu, s, off);
        if (lane == 0) sacc[a] = s;
    }
    __syncthreads();
    if (threadIdx.x == 0) {
        double c[M], S[M][M], W[M][M];
        for (int i = 0; i < M; i++) c[i] = sacc[i];
        int ai = M;
        for (int j = 0; j < M; j++)
            for (int k = j; k < M; k++) {
                S[j][k] = sacc[ai];
                S[k][j] = sacc[ai];
                ai++;
            }
        for (int i = 0; i < M; i++)
            for (int j = 0; j < M; j++) W[i][j] = (double)g_W[i * M + j];

        double WS[M][M], G[M][M], rhs[M];
        for (int i = 0; i < M; i++)
            for (int k = 0; k < M; k++) {
                double s = 0.0;
                for (int j = 0; j < M; j++) s += W[i][j] * S[j][k];
                WS[i][k] = s;
            }
        for (int i = 0; i < M; i++)
            for (int l = 0; l < M; l++) {
                double s = 0.0;
                for (int k = 0; k < M; k++) s += WS[i][k] * W[l][k];
                G[i][l] = s;
            }
        for (int i = 0; i < M; i++) G[i][i] += 1e-5 * (double)g_mask[i];
        for (int i = 0; i < M; i++) {
            double s = 0.0;
            for (int j = 0; j < M; j++) s += W[i][j] * c[j];
            rhs[i] = s;
        }
        // Gaussian elimination with partial pivoting
        for (int col = 0; col < M; col++) {
            int piv = col;
            for (int r = col + 1; r < M; r++)
                if (fabs(G[r][col]) > fabs(G[piv][col])) piv = r;
            if (piv != col) {
                for (int cc = 0; cc < M; cc++) {
                    double tmp = G[col][cc]; G[col][cc] = G[piv][cc]; G[piv][cc] = tmp;
                }
                double tb = rhs[col]; rhs[col] = rhs[piv]; rhs[piv] = tb;
            }
            double inv = 1.0 / G[col][col];
            for (int r = col + 1; r < M; r++) {
                double f = G[r][col] * inv;
                for (int cc = col; cc < M; cc++) G[r][cc] -= f * G[col][cc];
                rhs[r] -= f * rhs[col];
            }
        }
        double z[M];
        for (int r = M - 1; r >= 0; r--) {
            double s = rhs[r];
            for (int cc = r + 1; cc < M; cc++) s -= G[r][cc] * z[cc];
            z[r] = s / G[r][r];
        }
        for (int j = 0; j < M; j++) {
            double s = 0.0;
            for (int i = 0; i < M; i++) s += W[i][j] * z[i];
            g_y[j] = (float)s;
        }
    }
}

// ---------------------------------------------------------------------------
// Kernel 4: map pass (reverse order for L2 tail reuse)
//   out = dv * (g + t^T y) / eps
// ---------------------------------------------------------------------------
__global__ void __launch_bounds__(NTHREADS, 4)
kwng_pass2(const float* __restrict__ T, const float* __restrict__ g,
           float* __restrict__ out, int D) {
    float qpk[15], y[M];
#pragma unroll
    for (int i = 0; i < 15; i++) qpk[i] = g_qpk[i];
#pragma unroll
    for (int i = 0; i < M; i++) y[i] = g_y[i];

    const float4* __restrict__ T4 = (const float4*)T;
    const float4* __restrict__ g4 = (const float4*)g;
    float4* __restrict__ o4 = (float4*)out;
    const int n4 = D >> 2;
    const float inv_eps = 1.0f / 1e-5f;

    for (int i = blockIdx.x * blockDim.x + threadIdx.x; i < n4;
         i += gridDim.x * blockDim.x) {
        int idx = n4 - 1 - i;   // reverse: hit pass1's L2-resident tail first
        float4 tv[M];
#pragma unroll
        for (int j = 0; j < M; j++) tv[j] = T4[(size_t)j * n4 + idx];
        float4 gv = g4[idx];
        const float* tp = reinterpret_cast<const float*>(tv);
        const float* gp = reinterpret_cast<const float*>(&gv);
        float4 ov;
        float* op = reinterpret_cast<float*>(&ov);
#pragma unroll
        for (int lane = 0; lane < 4; lane++) {
            float t[M];
#pragma unroll
            for (int j = 0; j < M; j++) t[j] = tp[j * 4 + lane];
            float ss = 0.0f;
            int qi = 0;
#pragma unroll
            for (int j = 0; j < M; j++) {
                float inner = qpk[qi++] * t[j];
#pragma unroll
                for (int k = j + 1; k < M; k++)
                    inner = fmaf(qpk[qi++], t[k], inner);
                ss = fmaf(inner, t[j], ss);
            }
            float r  = rsqrtf(fmaxf(ss, 1e-37f));
            float dv = __fdividef(1.0f, fmaf(ss, r, 1e-8f));
            float cond = y[0] * t[0];
#pragma unroll
            for (int j = 1; j < M; j++) cond = fmaf(y[j], t[j], cond);
            op[lane] = dv * ((gp[lane] + cond) * inv_eps);
        }
        __stcs(&o4[idx], ov);
    }
}

// ---------------------------------------------------------------------------
extern "C" void kernel_launch(void* const* d_in, const int* in_sizes, int n_in,
                              void* d_out, int out_size) {
    const float* K = (const float*)d_in[0];   // [5,5]
    const float* T = (const float*)d_in[1];   // [5, D]
    const float* g = (const float*)d_in[2];   // [D]
    float* out = (float*)d_out;               // [D]
    int D = in_sizes[2];

    kwng_setup<<<1, 1>>>(K);
    kwng_pass1<<<NBLOCKS, NTHREADS>>>(T, g, D);
    kwng_reduce_solve<<<1, NACC * 32>>>();
    kwng_pass2<<<NBLOCKS, NTHREADS>>>(T, g, out, D);
}

// round 3
// speedup vs baseline: 2.1524x; 1.0104x over previous
#include <cuda_runtime.h>
#include <math.h>
#include <stdint.h>

#define M 5
#define NACC 20              // c[5] + packed upper Gram S[15]
#define NB1 592              // pass1 grid (148 SMs * 2 CTAs * 2 waves)
#define NB2 1184             // pass2 grid
#define NTHREADS 256

__device__ float  g_W[M * M];
__device__ float  g_qpk[15];         // Q = W^T W packed upper, off-diag doubled
__device__ float  g_mask[M];
__device__ float  g_y[M];
__device__ double g_partials[NB1 * NACC];

// ---- f32x2 packed helpers (sm_103a) ---------------------------------------
__device__ __forceinline__ uint64_t pk2(float a, float b) {
    uint64_t r;
    asm("mov.b64 %0, {%1, %2};" : "=l"(r) : "f"(a), "f"(b));
    return r;
}
__device__ __forceinline__ void upk2(float& a, float& b, uint64_t v) {
    asm("mov.b64 {%0, %1}, %2;" : "=f"(a), "=f"(b) : "l"(v));
}
__device__ __forceinline__ uint64_t fma2(uint64_t a, uint64_t b, uint64_t c) {
    uint64_t d;
    asm("fma.rn.f32x2 %0, %1, %2, %3;" : "=l"(d) : "l"(a), "l"(b), "l"(c));
    return d;
}
__device__ __forceinline__ uint64_t mul2(uint64_t a, uint64_t b) {
    uint64_t d;
    asm("mul.rn.f32x2 %0, %1, %2;" : "=l"(d) : "l"(a), "l"(b));
    return d;
}
__device__ __forceinline__ uint64_t add2(uint64_t a, uint64_t b) {
    uint64_t d;
    asm("add.rn.f32x2 %0, %1, %2;" : "=l"(d) : "l"(a), "l"(b));
    return d;
}
// dv = 1/(sqrt(ss)+1e-8) for both packed halves
__device__ __forceinline__ uint64_t dv2_from_ss2(uint64_t ss2) {
    float sa, sb;
    upk2(sa, sb, ss2);
    float ra = rsqrtf(fmaxf(sa, 1e-37f));
    float rb = rsqrtf(fmaxf(sb, 1e-37f));
    float da = __fdividef(1.0f, fmaf(sa, ra, 1e-8f));
    float db = __fdividef(1.0f, fmaf(sb, rb, 1e-8f));
    return pk2(da, db);
}

// ---------------------------------------------------------------------------
// Kernel 1: fp32 5x5 Jacobi eigendecomposition -> W, mask, Q packed
// ---------------------------------------------------------------------------
__global__ void kwng_setup(const float* __restrict__ K) {
    float a[M][M], v[M][M];
    for (int i = 0; i < M; i++)
        for (int j = 0; j < M; j++) {
            a[i][j] = K[i * M + j];
            v[i][j] = (i == j) ? 1.0f : 0.0f;
        }
    for (int sweep = 0; sweep < 12; sweep++) {
        float off = 0.0f;
        for (int p = 0; p < M; p++)
            for (int q = p + 1; q < M; q++) off += a[p][q] * a[p][q];
        if (off < 1e-18f) break;
        for (int p = 0; p < M; p++) {
            for (int q = p + 1; q < M; q++) {
                float apq = a[p][q];
                if (fabsf(apq) < 1e-30f) continue;
                float theta = (a[q][q] - a[p][p]) / (2.0f * apq);
                float t = ((theta >= 0.0f) ? 1.0f : -1.0f) /
                          (fabsf(theta) + sqrtf(theta * theta + 1.0f));
                float c = 1.0f / sqrtf(t * t + 1.0f);
                float s = t * c;
                for (int k = 0; k < M; k++) {
                    float akp = a[k][p], akq = a[k][q];
                    a[k][p] = c * akp - s * akq;
                    a[k][q] = s * akp + c * akq;
                }
                for (int k = 0; k < M; k++) {
                    float apk = a[p][k], aqk = a[q][k];
                    a[p][k] = c * apk - s * aqk;
                    a[q][k] = s * apk + c * aqk;
                }
                for (int k = 0; k < M; k++) {
                    float vkp = v[k][p], vkq = v[k][q];
                    v[k][p] = c * vkp - s * vkq;
                    v[k][q] = s * vkp + c * vkq;
                }
            }
        }
    }
    float W[M][M];
    for (int i = 0; i < M; i++) {
        float si = a[i][i];
        bool keep = si > 0.0f;                    // THRESH = 0
        g_mask[i] = keep ? 1.0f : 0.0f;
        float w = keep ? (1.0f / sqrtf(si)) : 0.0f;
        for (int j = 0; j < M; j++) {
            W[i][j] = w * v[j][i];
            g_W[i * M + j] = W[i][j];
        }
    }
    int qi = 0;
    for (int j = 0; j < M; j++)
        for (int k = j; k < M; k++) {
            float q = 0.0f;
            for (int i = 0; i < M; i++) q += W[i][j] * W[i][k];
            g_qpk[qi++] = (k == j) ? q : 2.0f * q;
        }
}

// ---------------------------------------------------------------------------
// Kernel 2: streaming reduction pass, f32x2-packed (lanes {0,1} and {2,3})
// ---------------------------------------------------------------------------
__global__ void __launch_bounds__(NTHREADS, 2)
kwng_pass1(const float* __restrict__ T, const float* __restrict__ g, int D) {
    uint64_t qpk2[15];
#pragma unroll
    for (int i = 0; i < 15; i++) {
        float q = g_qpk[i];
        qpk2[i] = pk2(q, q);
    }

    uint64_t acc2[NACC];
    const uint64_t zz = pk2(0.0f, 0.0f);
#pragma unroll
    for (int a = 0; a < NACC; a++) acc2[a] = zz;

    const float4* __restrict__ T4 = (const float4*)T;
    const float4* __restrict__ g4 = (const float4*)g;
    const int n4 = D >> 2;

    for (int idx = blockIdx.x * blockDim.x + threadIdx.x; idx < n4;
         idx += gridDim.x * blockDim.x) {
        float4 tv[M];
#pragma unroll
        for (int j = 0; j < M; j++) tv[j] = T4[(size_t)j * n4 + idx];
        float4 gv = g4[idx];
        const uint64_t* gpp = reinterpret_cast<const uint64_t*>(&gv);
#pragma unroll
        for (int pr = 0; pr < 2; pr++) {       // pair 0 = lanes(x,y), pair 1 = (z,w)
            uint64_t t2[M];
#pragma unroll
            for (int j = 0; j < M; j++)
                t2[j] = reinterpret_cast<const uint64_t*>(&tv[j])[pr];
            uint64_t g2 = gpp[pr];
            // ss = t^T Q t (packed upper, off-diag doubled)
            uint64_t ss2;
            {
                int qi = 0;
                uint64_t inner = mul2(qpk2[qi++], t2[0]);
#pragma unroll
                for (int k = 1; k < M; k++) inner = fma2(qpk2[qi++], t2[k], inner);
                ss2 = mul2(inner, t2[0]);
#pragma unroll
                for (int j = 1; j < M; j++) {
                    inner = mul2(qpk2[qi++], t2[j]);
#pragma unroll
                    for (int k = j + 1; k < M; k++)
                        inner = fma2(qpk2[qi++], t2[k], inner);
                    ss2 = fma2(inner, t2[j], ss2);
                }
            }
            uint64_t dv2 = dv2_from_ss2(ss2);
            uint64_t dvg2 = mul2(dv2, g2);
#pragma unroll
            for (int j = 0; j < M; j++) acc2[j] = fma2(t2[j], dvg2, acc2[j]);
            int ai = M;
#pragma unroll
            for (int j = 0; j < M; j++) {
                uint64_t u2 = mul2(dv2, t2[j]);
#pragma unroll
                for (int k = j; k < M; k++) {
                    acc2[ai] = fma2(u2, t2[k], acc2[ai]);
                    ai++;
                }
            }
        }
    }

    // collapse packed halves, then deterministic block reduction
    __shared__ float sred[NTHREADS / 32][NACC];
    int lane = threadIdx.x & 31;
    int warp = threadIdx.x >> 5;
#pragma unroll
    for (int a = 0; a < NACC; a++) {
        float lo, hi;
        upk2(lo, hi, acc2[a]);
        float v = lo + hi;
#pragma unroll
        for (int off = 16; off > 0; off >>= 1)
            v += __shfl_down_sync(0xffffffffu, v, off);
        if (lane == 0) sred[warp][a] = v;
    }
    __syncthreads();
    if (threadIdx.x < NACC) {
        double s = 0.0;
#pragma unroll
        for (int w = 0; w < NTHREADS / 32; w++) s += (double)sred[w][threadIdx.x];
        g_partials[(size_t)blockIdx.x * NACC + threadIdx.x] = s;
    }
}

// ---------------------------------------------------------------------------
// Kernel 3: reduce partials + tiny solve
//   G = W S W^T + eps*diag(mask);  z = G^{-1} (W c);  y = W^T z
// ---------------------------------------------------------------------------
__global__ void kwng_reduce_solve() {
    __shared__ double sacc[NACC];
    int a = threadIdx.x >> 5;
    int lane = threadIdx.x & 31;
    if (a < NACC) {
        double s = 0.0;
        for (int b = lane; b < NB1; b += 32)
            s += g_partials[(size_t)b * NACC + a];
#pragma unroll
        for (int off = 16; off > 0; off >>= 1)
            s += __shfl_down_sync(0xffffffffu, s, off);
        if (lane == 0) sacc[a] = s;
    }
    __syncthreads();
    if (threadIdx.x == 0) {
        double c[M], S[M][M], W[M][M];
        for (int i = 0; i < M; i++) c[i] = sacc[i];
        int ai = M;
        for (int j = 0; j < M; j++)
            for (int k = j; k < M; k++) {
                S[j][k] = sacc[ai];
                S[k][j] = sacc[ai];
                ai++;
            }
        for (int i = 0; i < M; i++)
            for (int j = 0; j < M; j++) W[i][j] = (double)g_W[i * M + j];

        double WS[M][M], G[M][M], rhs[M];
        for (int i = 0; i < M; i++)
            for (int k = 0; k < M; k++) {
                double s = 0.0;
                for (int j = 0; j < M; j++) s += W[i][j] * S[j][k];
                WS[i][k] = s;
            }
        for (int i = 0; i < M; i++)
            for (int l = 0; l < M; l++) {
                double s = 0.0;
                for (int k = 0; k < M; k++) s += WS[i][k] * W[l][k];
                G[i][l] = s;
            }
        for (int i = 0; i < M; i++) G[i][i] += 1e-5 * (double)g_mask[i];
        for (int i = 0; i < M; i++) {
            double s = 0.0;
            for (int j = 0; j < M; j++) s += W[i][j] * c[j];
            rhs[i] = s;
        }
        for (int col = 0; col < M; col++) {
            int piv = col;
            for (int r = col + 1; r < M; r++)
                if (fabs(G[r][col]) > fabs(G[piv][col])) piv = r;
            if (piv != col) {
                for (int cc = 0; cc < M; cc++) {
                    double tmp = G[col][cc]; G[col][cc] = G[piv][cc]; G[piv][cc] = tmp;
                }
                double tb = rhs[col]; rhs[col] = rhs[piv]; rhs[piv] = tb;
            }
            double inv = 1.0 / G[col][col];
            for (int r = col + 1; r < M; r++) {
                double f = G[r][col] * inv;
                for (int cc = col; cc < M; cc++) G[r][cc] -= f * G[col][cc];
                rhs[r] -= f * rhs[col];
            }
        }
        double z[M];
        for (int r = M - 1; r >= 0; r--) {
            double s = rhs[r];
            for (int cc = r + 1; cc < M; cc++) s -= G[r][cc] * z[cc];
            z[r] = s / G[r][r];
        }
        for (int j = 0; j < M; j++) {
            double s = 0.0;
            for (int i = 0; i < M; i++) s += W[i][j] * z[i];
            g_y[j] = (float)s;
        }
    }
}

// ---------------------------------------------------------------------------
// Kernel 4: map pass, f32x2-packed, reverse order for L2 tail reuse
//   out = dv * (g + t.y) / eps
// ---------------------------------------------------------------------------
__global__ void __launch_bounds__(NTHREADS, 4)
kwng_pass2(const float* __restrict__ T, const float* __restrict__ g,
           float* __restrict__ out, int D) {
    uint64_t qpk2[15], y2[M];
#pragma unroll
    for (int i = 0; i < 15; i++) {
        float q = g_qpk[i];
        qpk2[i] = pk2(q, q);
    }
#pragma unroll
    for (int i = 0; i < M; i++) {
        float yv = g_y[i];
        y2[i] = pk2(yv, yv);
    }
    const uint64_t eps2 = pk2(1e5f, 1e5f);   // 1/eps

    const float4* __restrict__ T4 = (const float4*)T;
    const float4* __restrict__ g4 = (const float4*)g;
    float4* __restrict__ o4 = (float4*)out;
    const int n4 = D >> 2;

    for (int i = blockIdx.x * blockDim.x + threadIdx.x; i < n4;
         i += gridDim.x * blockDim.x) {
        int idx = n4 - 1 - i;   // reverse: hit pass1's L2-resident tail first
        float4 tv[M];
#pragma unroll
        for (int j = 0; j < M; j++) tv[j] = T4[(size_t)j * n4 + idx];
        float4 gv = g4[idx];
        const uint64_t* gpp = reinterpret_cast<const uint64_t*>(&gv);
        float4 ov;
        uint64_t* opp = reinterpret_cast<uint64_t*>(&ov);
#pragma unroll
        for (int pr = 0; pr < 2; pr++) {
            uint64_t t2[M];
#pragma unroll
            for (int j = 0; j < M; j++)
                t2[j] = reinterpret_cast<const uint64_t*>(&tv[j])[pr];
            uint64_t ss2;
            {
                int qi = 0;
                uint64_t inner = mul2(qpk2[qi++], t2[0]);
#pragma unroll
                for (int k = 1; k < M; k++) inner = fma2(qpk2[qi++], t2[k], inner);
                ss2 = mul2(inner, t2[0]);
#pragma unroll
                for (int j = 1; j < M; j++) {
                    inner = mul2(qpk2[qi++], t2[j]);
#pragma unroll
                    for (int k = j + 1; k < M; k++)
                        inner = fma2(qpk2[qi++], t2[k], inner);
                    ss2 = fma2(inner, t2[j], ss2);
                }
            }
            uint64_t dv2 = dv2_from_ss2(ss2);
            uint64_t cond2 = mul2(y2[0], t2[0]);
#pragma unroll
            for (int j = 1; j < M; j++) cond2 = fma2(y2[j], t2[j], cond2);
            uint64_t s2 = add2(gpp[pr], cond2);
            s2 = mul2(s2, eps2);
            opp[pr] = mul2(dv2, s2);
        }
        __stcs(&o4[idx], ov);
    }
}

// ---------------------------------------------------------------------------
extern "C" void kernel_launch(void* const* d_in, const int* in_sizes, int n_in,
                              void* d_out, int out_size) {
    const float* K = (const float*)d_in[0];   // [5,5]
    const float* T = (const float*)d_in[1];   // [5, D]
    const float* g = (const float*)d_in[2];   // [D]
    float* out = (float*)d_out;               // [D]
    int D = in_sizes[2];

    kwng_setup<<<1, 1>>>(K);
    kwng_pass1<<<NB1, NTHREADS>>>(T, g, D);
    kwng_reduce_solve<<<1, NACC * 32>>>();
    kwng_pass2<<<NB2, NTHREADS>>>(T, g, out, D);
}